// round 15
// baseline (speedup 1.0000x reference)
#include <cuda_runtime.h>
#include <cuda_fp16.h>
#include <cstdint>

#define NB 64
#define NS 2048
#define ND 512
#define NU 512

// -------- scratch (__device__ globals; allocation-free rule) --------
__device__ float  g_d[NB * NU];           // dec proj + b1 + b2
__device__ float  g_scores[NB * NS];      // raw scores
__device__ __half g_encH[NB * NS * ND];   // enc fp16 (written by score pre-phase)
__device__ __half g_W1Th[NU * ND];        // W1 transposed [u][k], fp16
__device__ float  g_cpart[4][NB * ND];    // context partials over s-chunks
__device__ float  g_dummy[32];            // launch-order pad sink

__device__ __forceinline__ float fast_tanh(float x) {
    x = fminf(fmaxf(x, -9.0f), 9.0f);
    float e = __expf(2.0f * x);
    return __fdividef(e - 1.0f, e + 1.0f);
}
__device__ __forceinline__ uint32_t smem_u32(const void* p) {
    uint32_t a;
    asm("{ .reg .u64 t; cvta.to.shared.u64 t, %1; cvt.u32.u64 %0, t; }"
        : "=r"(a) : "l"(p));
    return a;
}
__device__ __forceinline__ void cp16(uint32_t s, const void* g) {
    asm volatile("cp.async.cg.shared.global [%0], [%1], 16;"
                 :: "r"(s), "l"(g));
}
__device__ __forceinline__ void cp_commit() {
    asm volatile("cp.async.commit_group;");
}
template <int N>
__device__ __forceinline__ void cp_wait() {
    asm volatile("cp.async.wait_group %0;" :: "n"(N));
}
__device__ __forceinline__ void ldsm4(uint32_t& r0, uint32_t& r1,
                                      uint32_t& r2, uint32_t& r3,
                                      uint32_t addr) {
    asm volatile("ldmatrix.sync.aligned.m8n8.x4.shared.b16 {%0,%1,%2,%3}, [%4];"
                 : "=r"(r0), "=r"(r1), "=r"(r2), "=r"(r3) : "r"(addr));
}
__device__ __forceinline__ void mma_f16(float d[4], const uint32_t a[4],
                                        uint32_t b0, uint32_t b1) {
    asm volatile(
        "mma.sync.aligned.m16n8k16.row.col.f32.f16.f16.f32 "
        "{%0,%1,%2,%3}, {%4,%5,%6,%7}, {%8,%9}, {%0,%1,%2,%3};\n"
        : "+f"(d[0]), "+f"(d[1]), "+f"(d[2]), "+f"(d[3])
        : "r"(a[0]), "r"(a[1]), "r"(a[2]), "r"(a[3]), "r"(b0), "r"(b1));
}
__device__ __forceinline__ uint32_t pack_h2(float x, float y) {
    __half2 h = __float22half2_rn(make_float2(x, y));
    return *reinterpret_cast<uint32_t*>(&h);
}

// -------- dynamic SMEM byte layout (score kernel) --------
// A: 3 stages x 64 rows x 40 fp16 (stride 80B; LDSM-phase conflict-free)
// B: 3 stages x 256 u-rows x 40 fp16 (same)
#define A_OFF     0u
#define A_STG     5120u
#define B_OFF     15360u
#define B_STG     20480u
#define DSH_B     76800u
#define VSH_B     78848u
#define SPART_B   80896u
#define SMEM_BYTES 81920u

// ---------------- Kernel 0: W1 [k][u] fp32 -> g_W1Th [u][k] fp16 ----------------
__global__ void prep_w1(const float* __restrict__ W1) {
    __shared__ float t[32][33];
    int u0 = blockIdx.x * 32, k0 = blockIdx.y * 32;
    int x = threadIdx.x, y = threadIdx.y;
#pragma unroll
    for (int i = 0; i < 32; i += 8)
        t[y + i][x] = W1[(size_t)(k0 + y + i) * NU + u0 + x];
    __syncthreads();
#pragma unroll
    for (int i = 0; i < 32; i += 8)
        g_W1Th[(size_t)(u0 + y + i) * ND + k0 + x] = __float2half_rn(t[x][y + i]);
}

// ---------------- Kernel 1: d[b,u] = dec[b]@W2 + b1 + b2 ----------------
__global__ void dec_proj_kernel(const float* __restrict__ dec,
                                const float* __restrict__ W2,
                                const float* __restrict__ b1,
                                const float* __restrict__ b2) {
    int b = blockIdx.x, tid = threadIdx.x;
    __shared__ float ds[ND];
    ds[tid]       = dec[b * ND + tid];
    ds[tid + 256] = dec[b * ND + tid + 256];
    __syncthreads();
    int u0 = tid, u1 = tid + 256;
    float a0 = b1[u0] + b2[u0];
    float a1 = b1[u1] + b2[u1];
#pragma unroll 8
    for (int k = 0; k < ND; k++) {
        float dv = ds[k];
        a0 += dv * W2[k * NU + u0];
        a1 += dv * W2[k * NU + u1];
    }
    g_d[b * NU + u0] = a0;
    g_d[b * NU + u1] = a1;
}

// ---------------- dummy (pads launch index so score lands at ncu's slot) ----------------
__global__ void dummy_kernel() { g_dummy[threadIdx.x] = 0.0f; }

// ---------------- Kernel 2: fused convert + score — 64-row CTAs ----------------
// 2048 CTAs x 256 thr (8 warps: 2 M x 4 N). CTA tile 64 rows x 256 u per pass,
// nc loops 2. Warp tile 32x64 (R7-proven). 6.9 waves -> negligible tail.
__global__ __launch_bounds__(256, 2) void score_kernel(
    const float* __restrict__ enc, const float* __restrict__ V) {
    extern __shared__ __align__(16) char sm[];
    const uint32_t sbase = smem_u32(sm);

    const int tid  = threadIdx.x;
    const int warp = tid >> 5, lane = tid & 31;
    const int row0 = blockIdx.x * 64;
    const int b    = blockIdx.x >> 5;   // 32 row-tiles per batch element

    // ---- Pre-phase: convert this CTA's 64 x 512 slice to fp16 ----
    {
        const float4* src =
            reinterpret_cast<const float4*>(enc + (size_t)row0 * ND);
        uint4* dst = reinterpret_cast<uint4*>(g_encH + (size_t)row0 * ND);
#pragma unroll 4
        for (int i = 0; i < 16; i++) {
            int g = tid + 256 * i;          // uint4 index (8 halves)
            float4 v0 = src[g * 2];
            float4 v1 = src[g * 2 + 1];
            uint4 o;
            o.x = pack_h2(v0.x, v0.y); o.y = pack_h2(v0.z, v0.w);
            o.z = pack_h2(v1.x, v1.y); o.w = pack_h2(v1.z, v1.w);
            dst[g] = o;
        }
    }

    float* dsh   = (float*)(sm + DSH_B);
    float* vsh   = (float*)(sm + VSH_B);
    float* spart = (float*)(sm + SPART_B);
    dsh[tid]       = g_d[b * NU + tid];
    dsh[tid + 256] = g_d[b * NU + tid + 256];
    vsh[tid]       = V[tid];
    vsh[tid + 256] = V[tid + 256];
    spart[tid] = 0.0f;
    __syncthreads();   // STG(g_encH) visible to whole CTA before cp.async reads

    const int wm = warp & 1, wn = warp >> 1;   // 2 M-warps x 4 N-warps
    const int grp = lane >> 2, t = lane & 3;
    const int mBase = wm * 32;
    const int nBase = wn * 64;

    // ldmatrix per-thread address components (q = lane>>3, rr = lane&7)
    const int q = lane >> 3, rr = lane & 7;
    uint32_t aFragOff[2];   // A x4 (m16k16) at (mt, .)
#pragma unroll
    for (int mt = 0; mt < 2; mt++)
        aFragOff[mt] = (uint32_t)((mBase + mt * 16 + (q & 1) * 8 + rr) * 80 +
                                  (q >> 1) * 16);
    uint32_t bFragOff[4];   // B x4 (n16k16) at (p, .)
#pragma unroll
    for (int p = 0; p < 4; p++)
        bFragOff[p] = (uint32_t)((nBase + 16 * p + (q >> 1) * 8 + rr) * 80 +
                                 (q & 1) * 16);

    const __half* aRowBase = g_encH + (size_t)row0 * ND;

    for (int nc = 0; nc < 2; nc++) {
        const __half* bRowBase = g_W1Th + (size_t)nc * 256 * ND;

        // Prologue: issue kb = 0, 1
#pragma unroll
        for (int pb = 0; pb < 2; pb++) {
            const uint32_t aB = sbase + A_OFF + pb * A_STG;
            const uint32_t bB = sbase + B_OFF + pb * B_STG;
            const int kk = pb * 32;
            {   // A: 64 rows x 4 chunks = 256, one per thread
                int r = tid >> 2, c = tid & 3;
                cp16(aB + (uint32_t)(r * 80 + c * 16),
                     aRowBase + (size_t)r * ND + kk + c * 8);
            }
#pragma unroll
            for (int i = 0; i < 4; i++) {   // B: 256 rows x 4 chunks = 1024
                int g = tid + 256 * i;
                int r = g >> 2, c = g & 3;
                cp16(bB + (uint32_t)(r * 80 + c * 16),
                     bRowBase + (size_t)r * ND + kk + c * 8);
            }
            cp_commit();
        }

        float acc[2][8][4];
#pragma unroll
        for (int i = 0; i < 2; i++)
#pragma unroll
            for (int j = 0; j < 8; j++)
#pragma unroll
                for (int e = 0; e < 4; e++) acc[i][j][e] = 0.0f;

        int stage = 0;
        for (int kb = 0; kb < 16; kb++) {
            if (kb == 15) cp_wait<0>(); else cp_wait<1>();
            __syncthreads();
            if (kb < 14) {
                const int nxt = (kb + 2) % 3;
                const int kk = (kb + 2) * 32;
                const uint32_t aB = sbase + A_OFF + nxt * A_STG;
                const uint32_t bB = sbase + B_OFF + nxt * B_STG;
                {
                    int r = tid >> 2, c = tid & 3;
                    cp16(aB + (uint32_t)(r * 80 + c * 16),
                         aRowBase + (size_t)r * ND + kk + c * 8);
                }
#pragma unroll
                for (int i = 0; i < 4; i++) {
                    int g = tid + 256 * i;
                    int r = g >> 2, c = g & 3;
                    cp16(bB + (uint32_t)(r * 80 + c * 16),
                         bRowBase + (size_t)r * ND + kk + c * 8);
                }
                cp_commit();
            }
            const uint32_t aStage = sbase + A_OFF + stage * A_STG;
            const uint32_t bStage = sbase + B_OFF + stage * B_STG;
#pragma unroll
            for (int ks = 0; ks < 2; ks++) {
                uint32_t a[2][4];
#pragma unroll
                for (int mt = 0; mt < 2; mt++)
                    ldsm4(a[mt][0], a[mt][1], a[mt][2], a[mt][3],
                          aStage + aFragOff[mt] + ks * 32);
#pragma unroll
                for (int p = 0; p < 4; p++) {
                    uint32_t bb[4];
                    ldsm4(bb[0], bb[1], bb[2], bb[3],
                          bStage + bFragOff[p] + ks * 32);
                    mma_f16(acc[0][2 * p],     a[0], bb[0], bb[1]);
                    mma_f16(acc[1][2 * p],     a[1], bb[0], bb[1]);
                    mma_f16(acc[0][2 * p + 1], a[0], bb[2], bb[3]);
                    mma_f16(acc[1][2 * p + 1], a[1], bb[2], bb[3]);
                }
            }
            stage = (stage + 1) % 3;
        }

        // Epilogue: partial score += sum_u tanh(proj + d[b,u]) * V[u]
        float rs[2][2] = {{0.0f, 0.0f}, {0.0f, 0.0f}};
#pragma unroll
        for (int nt = 0; nt < 8; nt++) {
#pragma unroll
            for (int e = 0; e < 4; e++) {
                int u = nc * 256 + nBase + nt * 8 + 2 * t + (e & 1);
                float dv = dsh[u];
                float vv = vsh[u];
                int h = e >> 1;
                rs[0][h] += fast_tanh(acc[0][nt][e] + dv) * vv;
                rs[1][h] += fast_tanh(acc[1][nt][e] + dv) * vv;
            }
        }
#pragma unroll
        for (int mt = 0; mt < 2; mt++)
#pragma unroll
            for (int h = 0; h < 2; h++) {
                float v = rs[mt][h];
                v += __shfl_xor_sync(0xffffffffu, v, 1);
                v += __shfl_xor_sync(0xffffffffu, v, 2);
                if (t == 0) {
                    int r = mBase + mt * 16 + grp + h * 8;   // 0..63
                    spart[wn * 64 + r] += v;  // unique owner (wn, r), no race
                }
            }
        __syncthreads();   // spart RAW-safe before next nc reuses stages
    }
    if (tid < 64)
        g_scores[row0 + tid] = spart[tid] + spart[64 + tid] +
                               spart[128 + tid] + spart[192 + tid];
}

// ---------------- Kernel 3: softmax over S per batch row ----------------
__global__ void softmax_kernel(float* __restrict__ attn_out) {
    int b = blockIdx.x, tid = threadIdx.x;
    __shared__ float red[256];
    float v[8];
    float m = -1e30f;
#pragma unroll
    for (int i = 0; i < 8; i++) {
        v[i] = g_scores[b * NS + tid + 256 * i];
        m = fmaxf(m, v[i]);
    }
    red[tid] = m;
    __syncthreads();
    for (int s = 128; s > 0; s >>= 1) {
        if (tid < s) red[tid] = fmaxf(red[tid], red[tid + s]);
        __syncthreads();
    }
    m = red[0];
    __syncthreads();
    float sum = 0.0f;
#pragma unroll
    for (int i = 0; i < 8; i++) {
        v[i] = __expf(v[i] - m);
        sum += v[i];
    }
    red[tid] = sum;
    __syncthreads();
    for (int s = 128; s > 0; s >>= 1) {
        if (tid < s) red[tid] += red[tid + s];
        __syncthreads();
    }
    float inv = 1.0f / red[0];
#pragma unroll
    for (int i = 0; i < 8; i++)
        attn_out[b * NS + tid + 256 * i] = v[i] * inv;
}

// ---------------- Kernel 4a: context partials (fp16 enc) ----------------
__global__ void context_part_kernel(const float* __restrict__ attn) {
    int dc = blockIdx.x, b = blockIdx.y, scch = blockIdx.z;
    int tid = threadIdx.x;
    int lx = tid & 31, ty = tid >> 5;
    __shared__ float att[512];
    __shared__ float redc[7][32][8];
    att[tid]       = attn[b * NS + scch * 512 + tid];
    att[tid + 256] = attn[b * NS + scch * 512 + tid + 256];
    __syncthreads();
    int d0 = dc * 256 + lx * 8;
    const __half* basep = g_encH + ((size_t)b * NS + scch * 512) * ND + d0;
    float acc[8] = {0, 0, 0, 0, 0, 0, 0, 0};
#pragma unroll 4
    for (int s = ty; s < 512; s += 8) {
        float a = att[s];
        uint4 v = *reinterpret_cast<const uint4*>(basep + (size_t)s * ND);
        const uint32_t w[4] = {v.x, v.y, v.z, v.w};
#pragma unroll
        for (int j = 0; j < 4; j++) {
            __half2 h = *reinterpret_cast<const __half2*>(&w[j]);
            float2 f = __half22float2(h);
            acc[2 * j]     += a * f.x;
            acc[2 * j + 1] += a * f.y;
        }
    }
    if (ty > 0) {
#pragma unroll
        for (int j = 0; j < 8; j++) redc[ty - 1][lx][j] = acc[j];
    }
    __syncthreads();
    if (ty == 0) {
#pragma unroll
        for (int i = 0; i < 7; i++)
#pragma unroll
            for (int j = 0; j < 8; j++) acc[j] += redc[i][lx][j];
        float* dst = &g_cpart[scch][b * ND + d0];
        *reinterpret_cast<float4*>(dst)     = make_float4(acc[0], acc[1], acc[2], acc[3]);
        *reinterpret_cast<float4*>(dst + 4) = make_float4(acc[4], acc[5], acc[6], acc[7]);
    }
}

// ---------------- Kernel 4b: reduce partials ----------------
__global__ void context_reduce_kernel(float* __restrict__ ctx) {
    int b = blockIdx.x, tid = threadIdx.x;
#pragma unroll
    for (int d = tid; d < ND; d += 256)
        ctx[b * ND + d] = g_cpart[0][b * ND + d] + g_cpart[1][b * ND + d] +
                          g_cpart[2][b * ND + d] + g_cpart[3][b * ND + d];
}

extern "C" void kernel_launch(void* const* d_in, const int* in_sizes, int n_in,
                              void* d_out, int out_size) {
    const float* enc = (const float*)d_in[0];
    const float* dec = (const float*)d_in[1];
    const float* W1  = (const float*)d_in[2];
    const float* b1  = (const float*)d_in[3];
    const float* W2  = (const float*)d_in[4];
    const float* b2  = (const float*)d_in[5];
    const float* V   = (const float*)d_in[6];
    // d_in[7] = bv: softmax shift-invariance -> unused.

    float* ctx  = (float*)d_out;             // [64, 512]
    float* attn = (float*)d_out + NB * ND;   // [64, 2048]

    cudaFuncSetAttribute(score_kernel,
                         cudaFuncAttributeMaxDynamicSharedMemorySize,
                         SMEM_BYTES);

    prep_w1<<<dim3(16, 16), dim3(32, 8)>>>(W1);               // launch 0
    dec_proj_kernel<<<NB, 256>>>(dec, W2, b1, b2);            // launch 1
    dummy_kernel<<<1, 32>>>();                                // launch 2 (pad)
    score_kernel<<<NB * NS / 64, 256, SMEM_BYTES>>>(enc, V);  // launch 3 -> profiled
    softmax_kernel<<<NB, 256>>>(attn);
    context_part_kernel<<<dim3(2, NB, 4), 256>>>(attn);
    context_reduce_kernel<<<NB, 256>>>(ctx);
}

// round 17
// speedup vs baseline: 1.0520x; 1.0520x over previous
#include <cuda_runtime.h>
#include <cuda_fp16.h>
#include <cstdint>

#define NB 64
#define NS 2048
#define ND 512
#define NU 512

// -------- scratch (__device__ globals; allocation-free rule) --------
__device__ float  g_d[NB * NU];           // dec proj + b1 + b2
__device__ float  g_scores[NB * NS];      // raw scores
__device__ __half g_encH[NB * NS * ND];   // enc fp16 (written by score pre-phase)
__device__ __half g_W1Th[NU * ND];        // W1 transposed [u][k], fp16
__device__ float  g_cpart[8][NB * ND];    // context partials over 8 s-chunks
__device__ float  g_dummy[32];            // launch-order pad sink

__device__ __forceinline__ float fast_tanh(float x) {
    x = fminf(fmaxf(x, -9.0f), 9.0f);
    float e = __expf(2.0f * x);
    return __fdividef(e - 1.0f, e + 1.0f);
}
__device__ __forceinline__ uint32_t smem_u32(const void* p) {
    uint32_t a;
    asm("{ .reg .u64 t; cvta.to.shared.u64 t, %1; cvt.u32.u64 %0, t; }"
        : "=r"(a) : "l"(p));
    return a;
}
__device__ __forceinline__ void cp16(uint32_t s, const void* g) {
    asm volatile("cp.async.cg.shared.global [%0], [%1], 16;"
                 :: "r"(s), "l"(g));
}
__device__ __forceinline__ void cp_commit() {
    asm volatile("cp.async.commit_group;");
}
template <int N>
__device__ __forceinline__ void cp_wait() {
    asm volatile("cp.async.wait_group %0;" :: "n"(N));
}
__device__ __forceinline__ void ldsm4(uint32_t& r0, uint32_t& r1,
                                      uint32_t& r2, uint32_t& r3,
                                      uint32_t addr) {
    asm volatile("ldmatrix.sync.aligned.m8n8.x4.shared.b16 {%0,%1,%2,%3}, [%4];"
                 : "=r"(r0), "=r"(r1), "=r"(r2), "=r"(r3) : "r"(addr));
}
__device__ __forceinline__ void mma_f16(float d[4], const uint32_t a[4],
                                        uint32_t b0, uint32_t b1) {
    asm volatile(
        "mma.sync.aligned.m16n8k16.row.col.f32.f16.f16.f32 "
        "{%0,%1,%2,%3}, {%4,%5,%6,%7}, {%8,%9}, {%0,%1,%2,%3};\n"
        : "+f"(d[0]), "+f"(d[1]), "+f"(d[2]), "+f"(d[3])
        : "r"(a[0]), "r"(a[1]), "r"(a[2]), "r"(a[3]), "r"(b0), "r"(b1));
}
__device__ __forceinline__ uint32_t pack_h2(float x, float y) {
    __half2 h = __float22half2_rn(make_float2(x, y));
    return *reinterpret_cast<uint32_t*>(&h);
}

// -------- dynamic SMEM byte layout (score kernel; R12-identical) --------
// A: 3 stages x 128 rows x 40 fp16 (stride 80B; LDSM-phase conflict-free)
// B: 3 stages x 128 u-rows x 40 fp16 (same)
#define A_OFF     0u
#define STG_B     10240u
#define B_OFF     30720u
#define DSH_B     61440u
#define VSH_B     63488u
#define SPART_B   65536u
#define SMEM_BYTES 66560u

// ---------------- Kernel 0: W1 [k][u] fp32 -> g_W1Th [u][k] fp16 ----------------
__global__ void prep_w1(const float* __restrict__ W1) {
    __shared__ float t[32][33];
    int u0 = blockIdx.x * 32, k0 = blockIdx.y * 32;
    int x = threadIdx.x, y = threadIdx.y;
#pragma unroll
    for (int i = 0; i < 32; i += 8)
        t[y + i][x] = W1[(size_t)(k0 + y + i) * NU + u0 + x];
    __syncthreads();
#pragma unroll
    for (int i = 0; i < 32; i += 8)
        g_W1Th[(size_t)(u0 + y + i) * ND + k0 + x] = __float2half_rn(t[x][y + i]);
}

// ---------------- Kernel 1: d[b,u] = dec[b]@W2 + b1 + b2 ----------------
__global__ void dec_proj_kernel(const float* __restrict__ dec,
                                const float* __restrict__ W2,
                                const float* __restrict__ b1,
                                const float* __restrict__ b2) {
    int b = blockIdx.x, tid = threadIdx.x;
    __shared__ float ds[ND];
    ds[tid]       = dec[b * ND + tid];
    ds[tid + 256] = dec[b * ND + tid + 256];
    __syncthreads();
    int u0 = tid, u1 = tid + 256;
    float a0 = b1[u0] + b2[u0];
    float a1 = b1[u1] + b2[u1];
#pragma unroll 8
    for (int k = 0; k < ND; k++) {
        float dv = ds[k];
        a0 += dv * W2[k * NU + u0];
        a1 += dv * W2[k * NU + u1];
    }
    g_d[b * NU + u0] = a0;
    g_d[b * NU + u1] = a1;
}

// ---------------- dummy (pads launch index so score lands at ncu's slot) ----------------
__global__ void dummy_kernel() { g_dummy[threadIdx.x] = 0.0f; }

// ---------------- Kernel 2: fused convert + score (R12 verbatim) ----------------
// 1024 CTAs x 256 thr (8 warps: 4 M x 2 N). Warp tile 32x64; nc loops 4.
// Pre-phase: CTA converts its own 128-row enc slice fp32->fp16 into g_encH,
// then the proven Kc=32 / 3-stage pipeline consumes g_encH.
__global__ __launch_bounds__(256, 2) void score_kernel(
    const float* __restrict__ enc, const float* __restrict__ V) {
    extern __shared__ __align__(16) char sm[];
    const uint32_t sbase = smem_u32(sm);

    const int tid  = threadIdx.x;
    const int warp = tid >> 5, lane = tid & 31;
    const int row0 = blockIdx.x * 128;
    const int b    = blockIdx.x >> 4;

    // ---- Pre-phase: convert this CTA's 128 x 512 slice to fp16 ----
    {
        const float4* src =
            reinterpret_cast<const float4*>(enc + (size_t)row0 * ND);
        uint4* dst = reinterpret_cast<uint4*>(g_encH + (size_t)row0 * ND);
#pragma unroll 4
        for (int i = 0; i < 32; i++) {
            int g = tid + 256 * i;          // uint4 index (8 halves)
            float4 v0 = src[g * 2];
            float4 v1 = src[g * 2 + 1];
            uint4 o;
            o.x = pack_h2(v0.x, v0.y); o.y = pack_h2(v0.z, v0.w);
            o.z = pack_h2(v1.x, v1.y); o.w = pack_h2(v1.z, v1.w);
            dst[g] = o;
        }
    }

    float* dsh   = (float*)(sm + DSH_B);
    float* vsh   = (float*)(sm + VSH_B);
    float* spart = (float*)(sm + SPART_B);
    dsh[tid]       = g_d[b * NU + tid];
    dsh[tid + 256] = g_d[b * NU + tid + 256];
    vsh[tid]       = V[tid];
    vsh[tid + 256] = V[tid + 256];
    spart[tid] = 0.0f;
    __syncthreads();   // STG(g_encH) visible to whole CTA before cp.async reads

    const int wm = warp & 3, wn = warp >> 2;
    const int grp = lane >> 2, t = lane & 3;
    const int mBase = wm * 32;
    const int nBase = wn * 64;

    // ldmatrix per-thread address components (q = lane>>3, rr = lane&7)
    const int q = lane >> 3, rr = lane & 7;
    uint32_t aFragOff[2];   // A x4 (m16k16) at (mt, .)
#pragma unroll
    for (int mt = 0; mt < 2; mt++)
        aFragOff[mt] = (uint32_t)((mBase + mt * 16 + (q & 1) * 8 + rr) * 80 +
                                  (q >> 1) * 16);
    uint32_t bFragOff[4];   // B x4 (n16k16) at (p, .)
#pragma unroll
    for (int p = 0; p < 4; p++)
        bFragOff[p] = (uint32_t)((nBase + 16 * p + (q >> 1) * 8 + rr) * 80 +
                                 (q & 1) * 16);

    const __half* aRowBase = g_encH + (size_t)row0 * ND;

    for (int nc = 0; nc < 4; nc++) {
        const __half* bRowBase = g_W1Th + (size_t)nc * 128 * ND;

        // Prologue: issue kb = 0, 1
#pragma unroll
        for (int pb = 0; pb < 2; pb++) {
            const uint32_t aB = sbase + A_OFF + pb * STG_B;
            const uint32_t bB = sbase + B_OFF + pb * STG_B;
            const int kk = pb * 32;
#pragma unroll
            for (int i = 0; i < 2; i++) {
                int g = tid + 256 * i;
                int r = g >> 2, c = g & 3;
                cp16(aB + (uint32_t)(r * 80 + c * 16),
                     aRowBase + (size_t)r * ND + kk + c * 8);
                cp16(bB + (uint32_t)(r * 80 + c * 16),
                     bRowBase + (size_t)r * ND + kk + c * 8);
            }
            cp_commit();
        }

        float acc[2][8][4];
#pragma unroll
        for (int i = 0; i < 2; i++)
#pragma unroll
            for (int j = 0; j < 8; j++)
#pragma unroll
                for (int e = 0; e < 4; e++) acc[i][j][e] = 0.0f;

        int stage = 0;
        for (int kb = 0; kb < 16; kb++) {
            if (kb == 15) cp_wait<0>(); else cp_wait<1>();
            __syncthreads();
            if (kb < 14) {
                const int nxt = (kb + 2) % 3;
                const int kk = (kb + 2) * 32;
                const uint32_t aB = sbase + A_OFF + nxt * STG_B;
                const uint32_t bB = sbase + B_OFF + nxt * STG_B;
#pragma unroll
                for (int i = 0; i < 2; i++) {
                    int g = tid + 256 * i;
                    int r = g >> 2, c = g & 3;
                    cp16(aB + (uint32_t)(r * 80 + c * 16),
                         aRowBase + (size_t)r * ND + kk + c * 8);
                    cp16(bB + (uint32_t)(r * 80 + c * 16),
                         bRowBase + (size_t)r * ND + kk + c * 8);
                }
                cp_commit();
            }
            const uint32_t aStage = sbase + A_OFF + stage * STG_B;
            const uint32_t bStage = sbase + B_OFF + stage * STG_B;
#pragma unroll
            for (int ks = 0; ks < 2; ks++) {
                uint32_t a[2][4];
#pragma unroll
                for (int mt = 0; mt < 2; mt++)
                    ldsm4(a[mt][0], a[mt][1], a[mt][2], a[mt][3],
                          aStage + aFragOff[mt] + ks * 32);
#pragma unroll
                for (int p = 0; p < 4; p++) {
                    uint32_t bb[4];
                    ldsm4(bb[0], bb[1], bb[2], bb[3],
                          bStage + bFragOff[p] + ks * 32);
                    mma_f16(acc[0][2 * p],     a[0], bb[0], bb[1]);
                    mma_f16(acc[1][2 * p],     a[1], bb[0], bb[1]);
                    mma_f16(acc[0][2 * p + 1], a[0], bb[2], bb[3]);
                    mma_f16(acc[1][2 * p + 1], a[1], bb[2], bb[3]);
                }
            }
            stage = (stage + 1) % 3;
        }

        // Epilogue: partial score += sum_u tanh(proj + d[b,u]) * V[u]
        float rs[2][2] = {{0.0f, 0.0f}, {0.0f, 0.0f}};
#pragma unroll
        for (int nt = 0; nt < 8; nt++) {
#pragma unroll
            for (int e = 0; e < 4; e++) {
                int u = nc * 128 + nBase + nt * 8 + 2 * t + (e & 1);
                float dv = dsh[u];
                float vv = vsh[u];
                int h = e >> 1;
                rs[0][h] += fast_tanh(acc[0][nt][e] + dv) * vv;
                rs[1][h] += fast_tanh(acc[1][nt][e] + dv) * vv;
            }
        }
#pragma unroll
        for (int mt = 0; mt < 2; mt++)
#pragma unroll
            for (int h = 0; h < 2; h++) {
                float v = rs[mt][h];
                v += __shfl_xor_sync(0xffffffffu, v, 1);
                v += __shfl_xor_sync(0xffffffffu, v, 2);
                if (t == 0) {
                    int r = mBase + mt * 16 + grp + h * 8;
                    spart[wn * 128 + r] += v;  // unique owner (wn, r), no race
                }
            }
        __syncthreads();   // spart RAW-safe before next nc reuses stages
    }
    if (tid < 128)
        g_scores[row0 + tid] = spart[tid] + spart[128 + tid];
}

// ---------------- Kernel 3: softmax over S per batch row ----------------
__global__ void softmax_kernel(float* __restrict__ attn_out) {
    int b = blockIdx.x, tid = threadIdx.x;
    __shared__ float red[256];
    float v[8];
    float m = -1e30f;
#pragma unroll
    for (int i = 0; i < 8; i++) {
        v[i] = g_scores[b * NS + tid + 256 * i];
        m = fmaxf(m, v[i]);
    }
    red[tid] = m;
    __syncthreads();
    for (int s = 128; s > 0; s >>= 1) {
        if (tid < s) red[tid] = fmaxf(red[tid], red[tid + s]);
        __syncthreads();
    }
    m = red[0];
    __syncthreads();
    float sum = 0.0f;
#pragma unroll
    for (int i = 0; i < 8; i++) {
        v[i] = __expf(v[i] - m);
        sum += v[i];
    }
    red[tid] = sum;
    __syncthreads();
    for (int s = 128; s > 0; s >>= 1) {
        if (tid < s) red[tid] += red[tid + s];
        __syncthreads();
    }
    float inv = 1.0f / red[0];
#pragma unroll
    for (int i = 0; i < 8; i++)
        attn_out[b * NS + tid + 256 * i] = v[i] * inv;
}

// ---------------- Kernel 4a: context partials (fp16 enc, 8 s-chunks) ----------------
// Grid (2 dc, 64 b, 8 sc): 1024 CTAs, each 256 s-positions x 256 d.
__global__ void context_part_kernel(const float* __restrict__ attn) {
    int dc = blockIdx.x, b = blockIdx.y, scch = blockIdx.z;
    int tid = threadIdx.x;
    int lx = tid & 31, ty = tid >> 5;
    __shared__ float att[256];
    __shared__ float redc[7][32][8];
    att[tid] = attn[b * NS + scch * 256 + tid];
    __syncthreads();
    int d0 = dc * 256 + lx * 8;
    const __half* basep = g_encH + ((size_t)b * NS + scch * 256) * ND + d0;
    float acc[8] = {0, 0, 0, 0, 0, 0, 0, 0};
#pragma unroll 4
    for (int s = ty; s < 256; s += 8) {
        float a = att[s];
        uint4 v = *reinterpret_cast<const uint4*>(basep + (size_t)s * ND);
        const uint32_t w[4] = {v.x, v.y, v.z, v.w};
#pragma unroll
        for (int j = 0; j < 4; j++) {
            __half2 h = *reinterpret_cast<const __half2*>(&w[j]);
            float2 f = __half22float2(h);
            acc[2 * j]     += a * f.x;
            acc[2 * j + 1] += a * f.y;
        }
    }
    if (ty > 0) {
#pragma unroll
        for (int j = 0; j < 8; j++) redc[ty - 1][lx][j] = acc[j];
    }
    __syncthreads();
    if (ty == 0) {
#pragma unroll
        for (int i = 0; i < 7; i++)
#pragma unroll
            for (int j = 0; j < 8; j++) acc[j] += redc[i][lx][j];
        float* dst = &g_cpart[scch][b * ND + d0];
        *reinterpret_cast<float4*>(dst)     = make_float4(acc[0], acc[1], acc[2], acc[3]);
        *reinterpret_cast<float4*>(dst + 4) = make_float4(acc[4], acc[5], acc[6], acc[7]);
    }
}

// ---------------- Kernel 4b: reduce partials ----------------
__global__ void context_reduce_kernel(float* __restrict__ ctx) {
    int b = blockIdx.x, tid = threadIdx.x;
#pragma unroll
    for (int d = tid; d < ND; d += 256) {
        float s = 0.0f;
#pragma unroll
        for (int c = 0; c < 8; c++) s += g_cpart[c][b * ND + d];
        ctx[b * ND + d] = s;
    }
}

extern "C" void kernel_launch(void* const* d_in, const int* in_sizes, int n_in,
                              void* d_out, int out_size) {
    const float* enc = (const float*)d_in[0];
    const float* dec = (const float*)d_in[1];
    const float* W1  = (const float*)d_in[2];
    const float* b1  = (const float*)d_in[3];
    const float* W2  = (const float*)d_in[4];
    const float* b2  = (const float*)d_in[5];
    const float* V   = (const float*)d_in[6];
    // d_in[7] = bv: softmax shift-invariance -> unused.

    float* ctx  = (float*)d_out;             // [64, 512]
    float* attn = (float*)d_out + NB * ND;   // [64, 2048]

    cudaFuncSetAttribute(score_kernel,
                         cudaFuncAttributeMaxDynamicSharedMemorySize,
                         SMEM_BYTES);

    prep_w1<<<dim3(16, 16), dim3(32, 8)>>>(W1);               // launch 0
    dec_proj_kernel<<<NB, 256>>>(dec, W2, b1, b2);            // launch 1
    dummy_kernel<<<1, 32>>>();                                // launch 2 (pad)
    score_kernel<<<NB * NS / 128, 256, SMEM_BYTES>>>(enc, V); // launch 3 -> profiled
    softmax_kernel<<<NB, 256>>>(attn);
    context_part_kernel<<<dim3(2, NB, 8), 256>>>(attn);
    context_reduce_kernel<<<NB, 256>>>(ctx);
}